// round 12
// baseline (speedup 1.0000x reference)
#include <cuda_runtime.h>
#include <cstdint>

#define BHN   48
#define SEQ   1024
#define HD    64
#define TQ    128
#define TK    64
#define NQT   8           // SEQ / TQ
#define NTHREADS 128
#define LAM   0.01f
#define EPSV  1e-6f
#define CLV   20.0f
#define SCALE 0.125f

#define STRQ  132         // qT / Sw row stride (floats)
#define STRK  68          // Kb / Vb row stride (floats)
#define SW_OFF  (64 * STRQ)
#define KB_OFF  (2 * 64 * STRQ)
#define VB_OFF  (KB_OFF + 64 * STRK)
#define SMEM_FLOATS (KB_OFF + 2 * 64 * STRK)

typedef unsigned long long u64;

__device__ __forceinline__ u64 pk2(float lo, float hi) {
    u64 r; asm("mov.b64 %0, {%1,%2};" : "=l"(r) : "f"(lo), "f"(hi)); return r;
}
__device__ __forceinline__ void unpk2(u64 v, float& lo, float& hi) {
    asm("mov.b64 {%0,%1}, %2;" : "=f"(lo), "=f"(hi) : "l"(v));
}
__device__ __forceinline__ void fma2(u64& d, u64 a, u64 b) {
    asm("fma.rn.f32x2 %0, %1, %2, %0;" : "+l"(d) : "l"(a), "l"(b));
}
__device__ __forceinline__ u64 mul2(u64 a, u64 b) {
    u64 r; asm("mul.rn.f32x2 %0, %1, %2;" : "=l"(r) : "l"(a), "l"(b)); return r;
}
// sigmoid(x) = 0.5*tanh(0.5x)+0.5 via single MUFU tanh.approx
__device__ __forceinline__ float sigm(float lg) {
    float t;
    asm("tanh.approx.f32 %0, %1;" : "=f"(t) : "f"(lg * 0.5f));
    return fmaf(t, 0.5f, 0.5f);
}

__global__ void __launch_bounds__(NTHREADS, 2)
rse_attn(const float* __restrict__ gq, const float* __restrict__ gk,
         const float* __restrict__ gv, const float* __restrict__ gcos,
         const float* __restrict__ gsin, float* __restrict__ gout)
{
    extern __shared__ float smem[];
    float* qT = smem;            // [d][q]  RoPE'd Q transposed, q = 0..127
    float* Sw = smem + SW_OFF;   // [k][q]  beta then w
    float* Kb = smem + KB_OFF;   // [k][d]  RoPE'd K tile
    float* Vb = smem + VB_OFF;   // [k][d]  V tile

    const int tid = threadIdx.x;
    const int idx = blockIdx.x;
    const int qt  = (NQT - 1) - (idx / BHN);   // heavy q-tiles first
    const int bh  = idx % BHN;
    const int q0  = qt * TQ;
    const size_t base = (size_t)bh * SEQ * HD;

    const int qg = tid & 15;      // 8-query group
    const int kg = tid >> 4;      // 8-key group (P1) / 8-dim group (P3)
    const int dg = kg;
    const int hrow  = tid >> 1;   // 0..63: loader row
    const int hhalf = tid & 1;

    // ---- one-time: load Q row, RoPE, store transposed qT[d][q] ----
    {
        const float* src = gq + base + (size_t)(q0 + tid) * HD;
        const float* cc  = gcos + (q0 + tid) * 32;
        const float* ss  = gsin + (q0 + tid) * 32;
        #pragma unroll
        for (int j = 0; j < 16; j++) {
            float4 x = *(const float4*)(src + 4 * j);
            float2 c = *(const float2*)(cc + 2 * j);
            float2 s = *(const float2*)(ss + 2 * j);
            qT[(4*j + 0) * STRQ + tid] = x.x * c.x - x.y * s.x;
            qT[(4*j + 1) * STRQ + tid] = x.y * c.x + x.x * s.x;
            qT[(4*j + 2) * STRQ + tid] = x.z * c.y - x.w * s.y;
            qT[(4*j + 3) * STRQ + tid] = x.w * c.y + x.z * s.y;
        }
    }
    // ---- prologue: load K(0), RoPE, into Kb ----
    {
        const float* src = gk + base + (size_t)hrow * HD + hhalf * 32;
        const float* cc  = gcos + hrow * 32 + hhalf * 16;
        const float* ss  = gsin + hrow * 32 + hhalf * 16;
        float* dst = Kb + hrow * STRK + hhalf * 32;
        #pragma unroll
        for (int j = 0; j < 8; j++) {
            float4 x = *(const float4*)(src + 4 * j);
            float2 c = *(const float2*)(cc + 2 * j);
            float2 s = *(const float2*)(ss + 2 * j);
            float4 kr;
            kr.x = x.x * c.x - x.y * s.x;
            kr.y = x.y * c.x + x.x * s.x;
            kr.z = x.z * c.y - x.w * s.y;
            kr.w = x.w * c.y + x.z * s.y;
            *(float4*)(dst + 4 * j) = kr;
        }
    }

    u64 acc[8][4];
    #pragma unroll
    for (int j = 0; j < 8; j++)
        #pragma unroll
        for (int i = 0; i < 4; i++) acc[j][i] = 0ull;
    float rem = 1.f, ws = 0.f;

    const int nchunk = 2 * qt + 2;
    for (int h = 0; h < nchunk; h++) {
        const int k0 = h * TK;
        // top barrier: P3(h-1) done (Sw/Vb free); K(h) resident in Kb
        __syncthreads();

        // ---- region A: P1(h): S[8k x 8q] = K·Qᵀ, fused beta -> Sw ----
        {
            u64 a[8][4];
            #pragma unroll
            for (int i = 0; i < 8; i++)
                #pragma unroll
                for (int j = 0; j < 4; j++) a[i][j] = 0ull;
            const float* kb = Kb + (kg * 8) * STRK;
            const float* qb = qT + qg * 8;

            #pragma unroll 2
            for (int ds = 0; ds < 16; ds++) {
                float4 kv[8];
                #pragma unroll
                for (int i = 0; i < 8; i++)
                    kv[i] = *(const float4*)(kb + i * STRK + ds * 4);
                #pragma unroll
                for (int j = 0; j < 4; j++) {
                    const float* qr = qb + (4 * ds + j) * STRQ;
                    float4 qa = *(const float4*)(qr);
                    float4 qc = *(const float4*)(qr + 4);
                    u64 v0 = pk2(qa.x, qa.y);
                    u64 v1 = pk2(qa.z, qa.w);
                    u64 v2 = pk2(qc.x, qc.y);
                    u64 v3 = pk2(qc.z, qc.w);
                    #pragma unroll
                    for (int i = 0; i < 8; i++) {
                        float ks = ((const float*)&kv[i])[j];
                        u64 s = pk2(ks, ks);
                        fma2(a[i][0], s, v0);
                        fma2(a[i][1], s, v1);
                        fma2(a[i][2], s, v2);
                        fma2(a[i][3], s, v3);
                    }
                }
            }
            const float fkq = (float)(k0 + kg * 8 - (q0 + qg * 8));
            #pragma unroll
            for (int i = 0; i < 8; i++) {
                float d0, d1, d2, d3, d4, d5, d6, d7;
                unpk2(a[i][0], d0, d1);
                unpk2(a[i][1], d2, d3);
                unpk2(a[i][2], d4, d5);
                unpk2(a[i][3], d6, d7);
                const float pd = (fkq + (float)i) * LAM;
                float4 b0, b1;
                b0.x = sigm(fminf(fmaxf(fmaf(d0, SCALE, pd            ), -CLV), CLV));
                b0.y = sigm(fminf(fmaxf(fmaf(d1, SCALE, pd - LAM      ), -CLV), CLV));
                b0.z = sigm(fminf(fmaxf(fmaf(d2, SCALE, pd - 2.f * LAM), -CLV), CLV));
                b0.w = sigm(fminf(fmaxf(fmaf(d3, SCALE, pd - 3.f * LAM), -CLV), CLV));
                b1.x = sigm(fminf(fmaxf(fmaf(d4, SCALE, pd - 4.f * LAM), -CLV), CLV));
                b1.y = sigm(fminf(fmaxf(fmaf(d5, SCALE, pd - 5.f * LAM), -CLV), CLV));
                b1.z = sigm(fminf(fmaxf(fmaf(d6, SCALE, pd - 6.f * LAM), -CLV), CLV));
                b1.w = sigm(fminf(fmaxf(fmaf(d7, SCALE, pd - 7.f * LAM), -CLV), CLV));
                float* sd = Sw + (kg * 8 + i) * STRQ + qg * 8;
                *(float4*)(sd)     = b0;
                *(float4*)(sd + 4) = b1;
            }
        }
        __syncthreads();

        // ---- region B: V LDGs (drain under scan) + scan + V store ----
        float4 vreg[8];
        {
            const float* src = gv + base + (size_t)(k0 + hrow) * HD + hhalf * 32;
            #pragma unroll
            for (int j = 0; j < 8; j++)
                vreg[j] = *(const float4*)(src + 4 * j);
        }
        if (h < 2 * qt) {          // full chunk: mask-free
            #pragma unroll 1
            for (int g = 0; g < 8; g++) {
                float b[8];
                #pragma unroll
                for (int j = 0; j < 8; j++)
                    b[j] = Sw[(g * 8 + j) * STRQ + tid];
                #pragma unroll
                for (int j = 0; j < 8; j++) {
                    float w = b[j] * rem;
                    rem = fmaf(-w, rem, rem);
                    ws += w;
                    b[j] = w;
                }
                rem = fmaxf(rem, EPSV);
                #pragma unroll
                for (int j = 0; j < 8; j++)
                    Sw[(g * 8 + j) * STRQ + tid] = b[j];
            }
        } else {                   // diagonal chunks: causal mask
            const int nvalid = min(64, max(0, tid + 1 - (k0 - q0)));
            #pragma unroll 1
            for (int g = 0; g < 8; g++) {
                float b[8];
                #pragma unroll
                for (int j = 0; j < 8; j++)
                    b[j] = Sw[(g * 8 + j) * STRQ + tid];
                #pragma unroll
                for (int j = 0; j < 8; j++) {
                    float w = (g * 8 + j < nvalid) ? b[j] * rem : 0.f;
                    rem = fmaf(-w, rem, rem);
                    ws += w;
                    b[j] = w;
                }
                rem = fmaxf(rem, EPSV);
                #pragma unroll
                for (int j = 0; j < 8; j++)
                    Sw[(g * 8 + j) * STRQ + tid] = b[j];
            }
        }
        {
            float* dst = Vb + hrow * STRK + hhalf * 32;
            #pragma unroll
            for (int j = 0; j < 8; j++)
                *(float4*)(dst + 4 * j) = vreg[j];
        }
        __syncthreads();

        // ---- region C: raw-K(h+1) LDGs (drain under P3) + P3 + RoPE+store ----
        float4 kreg[8];
        const bool pf = (h + 1 < nchunk);
        if (pf) {
            const float* src = gk + base + (size_t)(k0 + TK + hrow) * HD + hhalf * 32;
            #pragma unroll
            for (int j = 0; j < 8; j++)
                kreg[j] = *(const float4*)(src + 4 * j);
        }
        {
            const float* wb = Sw + qg * 8;
            const float* vb = Vb + dg * 8;
            #pragma unroll 2
            for (int k = 0; k < TK; k++) {
                float4 w0 = *(const float4*)(wb + k * STRQ);
                float4 w1 = *(const float4*)(wb + k * STRQ + 4);
                ulonglong2 va = *(const ulonglong2*)(vb + k * STRK);
                ulonglong2 vc = *(const ulonglong2*)(vb + k * STRK + 4);
                u64 s;
                s = pk2(w0.x, w0.x);
                fma2(acc[0][0], s, va.x); fma2(acc[0][1], s, va.y);
                fma2(acc[0][2], s, vc.x); fma2(acc[0][3], s, vc.y);
                s = pk2(w0.y, w0.y);
                fma2(acc[1][0], s, va.x); fma2(acc[1][1], s, va.y);
                fma2(acc[1][2], s, vc.x); fma2(acc[1][3], s, vc.y);
                s = pk2(w0.z, w0.z);
                fma2(acc[2][0], s, va.x); fma2(acc[2][1], s, va.y);
                fma2(acc[2][2], s, vc.x); fma2(acc[2][3], s, vc.y);
                s = pk2(w0.w, w0.w);
                fma2(acc[3][0], s, va.x); fma2(acc[3][1], s, va.y);
                fma2(acc[3][2], s, vc.x); fma2(acc[3][3], s, vc.y);
                s = pk2(w1.x, w1.x);
                fma2(acc[4][0], s, va.x); fma2(acc[4][1], s, va.y);
                fma2(acc[4][2], s, vc.x); fma2(acc[4][3], s, vc.y);
                s = pk2(w1.y, w1.y);
                fma2(acc[5][0], s, va.x); fma2(acc[5][1], s, va.y);
                fma2(acc[5][2], s, vc.x); fma2(acc[5][3], s, vc.y);
                s = pk2(w1.z, w1.z);
                fma2(acc[6][0], s, va.x); fma2(acc[6][1], s, va.y);
                fma2(acc[6][2], s, vc.x); fma2(acc[6][3], s, vc.y);
                s = pk2(w1.w, w1.w);
                fma2(acc[7][0], s, va.x); fma2(acc[7][1], s, va.y);
                fma2(acc[7][2], s, vc.x); fma2(acc[7][3], s, vc.y);
            }
        }
        if (pf) {
            // cos/sin loaded here (L2-hot, ~230cyc once) then RoPE + store
            const int kn = k0 + TK + hrow;
            const float* cc = gcos + kn * 32 + hhalf * 16;
            const float* ss = gsin + kn * 32 + hhalf * 16;
            float* dst = Kb + hrow * STRK + hhalf * 32;
            #pragma unroll
            for (int j = 0; j < 8; j++) {
                float2 c = *(const float2*)(cc + 2 * j);
                float2 s = *(const float2*)(ss + 2 * j);
                float4 x = kreg[j];
                float4 kr;
                kr.x = x.x * c.x - x.y * s.x;
                kr.y = x.y * c.x + x.x * s.x;
                kr.z = x.z * c.y - x.w * s.y;
                kr.w = x.w * c.y + x.z * s.y;
                *(float4*)(dst + 4 * j) = kr;
            }
        }
    }

    // ---- epilogue: share wsum via Sw row 0, normalize, write out ----
    __syncthreads();
    Sw[tid] = ws;
    __syncthreads();
    float4 s0 = *(const float4*)(Sw + qg * 8);
    float4 s1 = *(const float4*)(Sw + qg * 8 + 4);
    float inv[8];
    inv[0] = __fdividef(1.f, fmaxf(s0.x, EPSV));
    inv[1] = __fdividef(1.f, fmaxf(s0.y, EPSV));
    inv[2] = __fdividef(1.f, fmaxf(s0.z, EPSV));
    inv[3] = __fdividef(1.f, fmaxf(s0.w, EPSV));
    inv[4] = __fdividef(1.f, fmaxf(s1.x, EPSV));
    inv[5] = __fdividef(1.f, fmaxf(s1.y, EPSV));
    inv[6] = __fdividef(1.f, fmaxf(s1.z, EPSV));
    inv[7] = __fdividef(1.f, fmaxf(s1.w, EPSV));
    #pragma unroll
    for (int j = 0; j < 8; j++) {
        u64 iv = pk2(inv[j], inv[j]);
        float* dst = gout + base + (size_t)(q0 + qg * 8 + j) * HD + dg * 8;
        ulonglong2 o;
        o.x = mul2(acc[j][0], iv);
        o.y = mul2(acc[j][1], iv);
        *(ulonglong2*)(dst) = o;
        o.x = mul2(acc[j][2], iv);
        o.y = mul2(acc[j][3], iv);
        *(ulonglong2*)(dst + 4) = o;
    }
}

extern "C" void kernel_launch(void* const* d_in, const int* in_sizes, int n_in,
                              void* d_out, int out_size)
{
    (void)in_sizes; (void)n_in; (void)out_size;
    const float* q    = (const float*)d_in[0];
    const float* k    = (const float*)d_in[1];
    const float* v    = (const float*)d_in[2];
    const float* cosc = (const float*)d_in[3];
    const float* sinc = (const float*)d_in[4];
    float* out = (float*)d_out;

    const int smem_bytes = SMEM_FLOATS * (int)sizeof(float);  // 102,400 B
    cudaFuncSetAttribute(rse_attn, cudaFuncAttributeMaxDynamicSharedMemorySize,
                         smem_bytes);
    rse_attn<<<NQT * BHN, NTHREADS, smem_bytes>>>(q, k, v, cosc, sinc, out);
}

// round 14
// speedup vs baseline: 2.4917x; 2.4917x over previous
#include <cuda_runtime.h>
#include <cuda_fp16.h>
#include <cstdint>

#define BHN   48
#define SEQ   1024
#define HD    64
#define TQ    128
#define TK    64
#define NQT   8           // SEQ / TQ
#define NTH   128
#define LAM   0.01f
#define EPSV  1e-6f
#define CLV   20.0f
#define SCALE 0.125f

// half rows padded to 72 halves = 144 bytes (16B-aligned, conflict-spread)
#define RSTR  144
#define QH_OFF 0
#define KH_OFF (QH_OFF + 128 * RSTR)   // 18432
#define VH_OFF (KH_OFF +  64 * RSTR)   // 27648
#define WH_OFF (VH_OFF +  64 * RSTR)   // 36864
#define WS_OFF (WH_OFF + 128 * RSTR)   // 55296
#define SM_TOTAL (WS_OFF + 128 * 4)    // 55808

__device__ __forceinline__ uint32_t s2u(const void* p) {
    uint32_t a;
    asm("{ .reg .u64 t; cvta.to.shared.u64 t, %1; cvt.u32.u64 %0, t; }" : "=r"(a) : "l"(p));
    return a;
}
__device__ __forceinline__ float sigm(float x) {
    float t;
    asm("tanh.approx.f32 %0, %1;" : "=f"(t) : "f"(x * 0.5f));
    return fmaf(t, 0.5f, 0.5f);
}
__device__ __forceinline__ void ldsm4(uint32_t* r, uint32_t addr) {
    asm volatile("ldmatrix.sync.aligned.m8n8.x4.shared.b16 {%0,%1,%2,%3}, [%4];"
        : "=r"(r[0]), "=r"(r[1]), "=r"(r[2]), "=r"(r[3]) : "r"(addr));
}
__device__ __forceinline__ void ldsm4t(uint32_t* r, uint32_t addr) {
    asm volatile("ldmatrix.sync.aligned.m8n8.x4.trans.shared.b16 {%0,%1,%2,%3}, [%4];"
        : "=r"(r[0]), "=r"(r[1]), "=r"(r[2]), "=r"(r[3]) : "r"(addr));
}
__device__ __forceinline__ void mma16816(float* d, const uint32_t* a, const uint32_t* b) {
    asm volatile(
        "mma.sync.aligned.m16n8k16.row.col.f32.f16.f16.f32 "
        "{%0,%1,%2,%3}, {%4,%5,%6,%7}, {%8,%9}, {%0,%1,%2,%3};"
        : "+f"(d[0]), "+f"(d[1]), "+f"(d[2]), "+f"(d[3])
        : "r"(a[0]), "r"(a[1]), "r"(a[2]), "r"(a[3]), "r"(b[0]), "r"(b[1]));
}

__global__ void __launch_bounds__(NTH, 2)
rse_mma(const float* __restrict__ gq, const float* __restrict__ gk,
        const float* __restrict__ gv, const float* __restrict__ gcos,
        const float* __restrict__ gsin, float* __restrict__ gout)
{
    extern __shared__ char smem[];
    const uint32_t sb = s2u(smem);
    const int tid  = threadIdx.x;
    const int wid  = tid >> 5;
    const int lane = tid & 31;
    const int idx  = blockIdx.x;
    const int qt   = (NQT - 1) - (idx / BHN);   // heavy q-tiles first
    const int bh   = idx % BHN;
    const int q0   = qt * TQ;
    const size_t base = (size_t)bh * SEQ * HD;

    // ---- load Q row (one per thread), RoPE, convert fp16 -> QH ----
    {
        const float* src = gq + base + (size_t)(q0 + tid) * HD;
        const float* cc  = gcos + (q0 + tid) * 32;
        const float* ss  = gsin + (q0 + tid) * 32;
        __half2* dst = (__half2*)(smem + QH_OFF + tid * RSTR);
        #pragma unroll
        for (int j = 0; j < 16; j++) {
            float4 x = *(const float4*)(src + 4 * j);
            float2 c = *(const float2*)(cc + 2 * j);
            float2 s = *(const float2*)(ss + 2 * j);
            dst[2*j]   = __floats2half2_rn(x.x*c.x - x.y*s.x, x.y*c.x + x.x*s.x);
            dst[2*j+1] = __floats2half2_rn(x.z*c.y - x.w*s.y, x.w*c.y + x.z*s.y);
        }
    }
    __syncthreads();

    // ---- Q fragments (persistent): A-layout, [mf][ks][4] ----
    uint32_t qf[2][4][4];
    {
        const uint32_t qbase = sb + QH_OFF;
        #pragma unroll
        for (int mf = 0; mf < 2; mf++)
            #pragma unroll
            for (int ks = 0; ks < 4; ks++) {
                int row  = 32 * wid + 16 * mf + (lane & 15);
                int colb = 32 * ks + ((lane & 16) ? 16 : 0);
                ldsm4(qf[mf][ks], qbase + row * RSTR + colb);
            }
    }

    float od[2][8][4];
    #pragma unroll
    for (int mf = 0; mf < 2; mf++)
        #pragma unroll
        for (int c = 0; c < 8; c++)
            #pragma unroll
            for (int r = 0; r < 4; r++) od[mf][c][r] = 0.f;
    float rem = 1.f, ws = 0.f;

    const uint32_t khb = sb + KH_OFF;
    const uint32_t vhb = sb + VH_OFF;
    const uint32_t whb = sb + WH_OFF;
    const int lrow  = tid >> 1;       // K/V loader row 0..63
    const int lhalf = tid & 1;        // half-row (32 floats)

    const int nchunk = 2 * qt + 2;
    for (int h = 0; h < nchunk; h++) {
        const int k0 = h * TK;
        __syncthreads();   // prev chunk's P3 done reading KH/VH/WH

        // ---- load K (RoPE) and V chunk -> fp16 smem ----
        {
            const float* ksrc = gk + base + (size_t)(k0 + lrow) * HD + lhalf * 32;
            const float* vsrc = gv + base + (size_t)(k0 + lrow) * HD + lhalf * 32;
            const float* cc   = gcos + (k0 + lrow) * 32 + lhalf * 16;
            const float* ss   = gsin + (k0 + lrow) * 32 + lhalf * 16;
            __half2* kdst = (__half2*)(smem + KH_OFF + lrow * RSTR + lhalf * 64);
            __half2* vdst = (__half2*)(smem + VH_OFF + lrow * RSTR + lhalf * 64);
            #pragma unroll
            for (int j = 0; j < 8; j++) {
                float4 x = *(const float4*)(ksrc + 4 * j);
                float2 c = *(const float2*)(cc + 2 * j);
                float2 s = *(const float2*)(ss + 2 * j);
                kdst[2*j]   = __floats2half2_rn(x.x*c.x - x.y*s.x, x.y*c.x + x.x*s.x);
                kdst[2*j+1] = __floats2half2_rn(x.z*c.y - x.w*s.y, x.w*c.y + x.z*s.y);
                float4 v = *(const float4*)(vsrc + 4 * j);
                vdst[2*j]   = __floats2half2_rn(v.x, v.y);
                vdst[2*j+1] = __floats2half2_rn(v.z, v.w);
            }
        }
        __syncthreads();

        // ---- P1: S[32q x 64k] per warp = Q · K^T (HMMA), fused beta -> WH ----
        {
            float sd[2][8][4];
            #pragma unroll
            for (int mf = 0; mf < 2; mf++)
                #pragma unroll
                for (int nf = 0; nf < 8; nf++)
                    #pragma unroll
                    for (int r = 0; r < 4; r++) sd[mf][nf][r] = 0.f;

            #pragma unroll
            for (int ks = 0; ks < 4; ks++) {
                uint32_t bf[8][2];
                #pragma unroll
                for (int a2 = 0; a2 < 4; a2++) {
                    uint32_t r[4];
                    int row  = 16 * a2 + (lane & 7) + ((lane & 16) ? 8 : 0);
                    int colb = 32 * ks + ((lane & 8) ? 16 : 0);
                    ldsm4(r, khb + row * RSTR + colb);
                    bf[2*a2][0]   = r[0]; bf[2*a2][1]   = r[1];
                    bf[2*a2+1][0] = r[2]; bf[2*a2+1][1] = r[3];
                }
                #pragma unroll
                for (int mf = 0; mf < 2; mf++)
                    #pragma unroll
                    for (int nf = 0; nf < 8; nf++)
                        mma16816(sd[mf][nf], qf[mf][ks], bf[nf]);
            }
            // beta epilogue: thread holds S[q, k] and S[q, k+1] (+8-row twin)
            #pragma unroll
            for (int mf = 0; mf < 2; mf++) {
                const int ql = 32 * wid + 16 * mf + (lane >> 2);
                const float pda = (float)(k0 - (q0 + ql)) * LAM;      // (k - q)*LAM at k=k0
                const float pdb = (float)(k0 - (q0 + ql + 8)) * LAM;
                #pragma unroll
                for (int nf = 0; nf < 8; nf++) {
                    const int kl = 8 * nf + 2 * (lane & 3);
                    float p0 = pda + (float)kl * LAM;
                    float b0 = sigm(fminf(fmaxf(fmaf(sd[mf][nf][0], SCALE, p0      ), -CLV), CLV));
                    float b1 = sigm(fminf(fmaxf(fmaf(sd[mf][nf][1], SCALE, p0 + LAM), -CLV), CLV));
                    *(__half2*)(smem + WH_OFF + ql * RSTR + kl * 2) = __floats2half2_rn(b0, b1);
                    float p1 = pdb + (float)kl * LAM;
                    float b2 = sigm(fminf(fmaxf(fmaf(sd[mf][nf][2], SCALE, p1      ), -CLV), CLV));
                    float b3 = sigm(fminf(fmaxf(fmaf(sd[mf][nf][3], SCALE, p1 + LAM), -CLV), CLV));
                    *(__half2*)(smem + WH_OFF + (ql + 8) * RSTR + kl * 2) = __floats2half2_rn(b2, b3);
                }
            }
        }
        __syncwarp();

        // ---- scan: thread = query tid; sequential over 64 keys ----
        {
            const int nvalid = min(64, max(0, tid + q0 - k0 + 1));
            uint4* wr = (uint4*)(smem + WH_OFF + tid * RSTR);
            #pragma unroll
            for (int g = 0; g < 8; g++) {
                uint4 u = wr[g];
                uint32_t* uw = (uint32_t*)&u;
                #pragma unroll
                for (int m = 0; m < 4; m++) {
                    float2 f = __half22float2(*(__half2*)&uw[m]);
                    int i = g * 8 + m * 2;
                    float w0 = (i < nvalid) ? f.x * rem : 0.f;
                    rem = fmaf(-w0, rem, rem);
                    float w1 = (i + 1 < nvalid) ? f.y * rem : 0.f;
                    rem = fmaf(-w1, rem, rem);
                    ws += w0 + w1;
                    __half2 o = __floats2half2_rn(w0, w1);
                    uw[m] = *(uint32_t*)&o;
                }
                rem = fmaxf(rem, EPSV);
                wr[g] = u;
            }
        }
        __syncwarp();

        // ---- P3: O[32q x 64d] per warp += W · V (HMMA, contraction = keys) ----
        #pragma unroll
        for (int ks2 = 0; ks2 < 4; ks2++) {
            uint32_t af[2][4];
            #pragma unroll
            for (int mf = 0; mf < 2; mf++) {
                int row  = 32 * wid + 16 * mf + (lane & 15);
                int colb = 32 * ks2 + ((lane & 16) ? 16 : 0);
                ldsm4(af[mf], whb + row * RSTR + colb);
            }
            uint32_t vb[8][2];
            #pragma unroll
            for (int c2 = 0; c2 < 4; c2++) {
                uint32_t r[4];
                int row  = 16 * ks2 + (lane & 7) + ((lane & 8) ? 8 : 0);
                int colb = 32 * c2 + ((lane & 16) ? 16 : 0);
                ldsm4t(r, vhb + row * RSTR + colb);
                vb[2*c2][0]   = r[0]; vb[2*c2][1]   = r[1];
                vb[2*c2+1][0] = r[2]; vb[2*c2+1][1] = r[3];
            }
            #pragma unroll
            for (int mf = 0; mf < 2; mf++)
                #pragma unroll
                for (int c = 0; c < 8; c++)
                    mma16816(od[mf][c], af[mf], vb[c]);
        }
    }

    // ---- epilogue: share wsum, normalize O fragments, write out ----
    {
        float* wsF = (float*)(smem + WS_OFF);
        wsF[tid] = ws;
        __syncthreads();
        #pragma unroll
        for (int mf = 0; mf < 2; mf++) {
            const int ql = 32 * wid + 16 * mf + (lane >> 2);
            float inv0 = __fdividef(1.f, fmaxf(wsF[ql],     EPSV));
            float inv1 = __fdividef(1.f, fmaxf(wsF[ql + 8], EPSV));
            float* r0 = gout + base + (size_t)(q0 + ql) * HD;
            float* r1 = r0 + 8 * HD;
            #pragma unroll
            for (int c = 0; c < 8; c++) {
                const int dc = 8 * c + 2 * (lane & 3);
                float2 o0; o0.x = od[mf][c][0] * inv0; o0.y = od[mf][c][1] * inv0;
                *(float2*)(r0 + dc) = o0;
                float2 o1; o1.x = od[mf][c][2] * inv1; o1.y = od[mf][c][3] * inv1;
                *(float2*)(r1 + dc) = o1;
            }
        }
    }
}

extern "C" void kernel_launch(void* const* d_in, const int* in_sizes, int n_in,
                              void* d_out, int out_size)
{
    (void)in_sizes; (void)n_in; (void)out_size;
    const float* q    = (const float*)d_in[0];
    const float* k    = (const float*)d_in[1];
    const float* v    = (const float*)d_in[2];
    const float* cosc = (const float*)d_in[3];
    const float* sinc = (const float*)d_in[4];
    float* out = (float*)d_out;

    cudaFuncSetAttribute(rse_mma, cudaFuncAttributeMaxDynamicSharedMemorySize,
                         SM_TOTAL);
    rse_mma<<<NQT * BHN, NTH, SM_TOTAL>>>(q, k, v, cosc, sinc, out);
}

// round 15
// speedup vs baseline: 3.1231x; 1.2534x over previous
#include <cuda_runtime.h>
#include <cuda_fp16.h>
#include <cstdint>

#define BHN   48
#define SEQ   1024
#define HD    64
#define TQ    128
#define TK    64
#define NQT   8           // SEQ / TQ
#define NTH   256
#define LAM   0.01f
#define EPSV  1e-6f
#define CLV   20.0f
#define SCALE 0.125f

// half rows padded to 72 halves = 144 bytes
#define RSTR  144
#define QH_OFF 0
#define KH_OFF (QH_OFF + 128 * RSTR)   // 18432
#define VH_OFF (KH_OFF +  64 * RSTR)   // 27648
#define WH_OFF (VH_OFF +  64 * RSTR)   // 36864
#define WS_OFF (WH_OFF + 128 * RSTR)   // 55296
#define SM_TOTAL (WS_OFF + 128 * 4)    // 55808

__device__ __forceinline__ uint32_t s2u(const void* p) {
    uint32_t a;
    asm("{ .reg .u64 t; cvta.to.shared.u64 t, %1; cvt.u32.u64 %0, t; }" : "=r"(a) : "l"(p));
    return a;
}
__device__ __forceinline__ float sigm(float x) {
    float t;
    asm("tanh.approx.f32 %0, %1;" : "=f"(t) : "f"(x * 0.5f));
    return fmaf(t, 0.5f, 0.5f);
}
__device__ __forceinline__ void ldsm4(uint32_t* r, uint32_t addr) {
    asm volatile("ldmatrix.sync.aligned.m8n8.x4.shared.b16 {%0,%1,%2,%3}, [%4];"
        : "=r"(r[0]), "=r"(r[1]), "=r"(r[2]), "=r"(r[3]) : "r"(addr));
}
__device__ __forceinline__ void ldsm4t(uint32_t* r, uint32_t addr) {
    asm volatile("ldmatrix.sync.aligned.m8n8.x4.trans.shared.b16 {%0,%1,%2,%3}, [%4];"
        : "=r"(r[0]), "=r"(r[1]), "=r"(r[2]), "=r"(r[3]) : "r"(addr));
}
__device__ __forceinline__ void mma16816(float* d, const uint32_t* a, const uint32_t* b) {
    asm volatile(
        "mma.sync.aligned.m16n8k16.row.col.f32.f16.f16.f32 "
        "{%0,%1,%2,%3}, {%4,%5,%6,%7}, {%8,%9}, {%0,%1,%2,%3};"
        : "+f"(d[0]), "+f"(d[1]), "+f"(d[2]), "+f"(d[3])
        : "r"(a[0]), "r"(a[1]), "r"(a[2]), "r"(a[3]), "r"(b[0]), "r"(b[1]));
}

__global__ void __launch_bounds__(NTH, 2)
rse_mma(const float* __restrict__ gq, const float* __restrict__ gk,
        const float* __restrict__ gv, const float* __restrict__ gcos,
        const float* __restrict__ gsin, float* __restrict__ gout)
{
    extern __shared__ char smem[];
    const uint32_t sb = s2u(smem);
    const int tid  = threadIdx.x;
    const int wid  = tid >> 5;     // 0..7, warp owns query rows 16*wid..16*wid+15
    const int lane = tid & 31;
    const int idx  = blockIdx.x;
    const int qt   = (NQT - 1) - (idx / BHN);   // heavy q-tiles first
    const int bh   = idx % BHN;
    const int q0   = qt * TQ;
    const size_t base = (size_t)bh * SEQ * HD;

    // ---- load Q (half-row per thread), RoPE, fp16 -> QH ----
    {
        const int row  = tid >> 1;
        const int half = tid & 1;
        const float* src = gq + base + (size_t)(q0 + row) * HD + half * 32;
        const float* cc  = gcos + (q0 + row) * 32 + half * 16;
        const float* ss  = gsin + (q0 + row) * 32 + half * 16;
        __half2* dst = (__half2*)(smem + QH_OFF + row * RSTR + half * 64);
        #pragma unroll
        for (int j = 0; j < 8; j++) {
            float4 x = *(const float4*)(src + 4 * j);
            float2 c = *(const float2*)(cc + 2 * j);
            float2 s = *(const float2*)(ss + 2 * j);
            dst[2*j]   = __floats2half2_rn(x.x*c.x - x.y*s.x, x.y*c.x + x.x*s.x);
            dst[2*j+1] = __floats2half2_rn(x.z*c.y - x.w*s.y, x.w*c.y + x.z*s.y);
        }
    }
    __syncthreads();

    // ---- Q fragments (persistent): warp's 16 rows, [ks][4] ----
    uint32_t qf[4][4];
    {
        const uint32_t qbase = sb + QH_OFF;
        const int row  = 16 * wid + (lane & 15);
        #pragma unroll
        for (int ks = 0; ks < 4; ks++) {
            int colb = 32 * ks + ((lane & 16) ? 16 : 0);
            ldsm4(qf[ks], qbase + row * RSTR + colb);
        }
    }

    float od[8][4];
    #pragma unroll
    for (int c = 0; c < 8; c++)
        #pragma unroll
        for (int r = 0; r < 4; r++) od[c][r] = 0.f;
    float rem = 1.f, ws = 0.f;
    const int sq = 16 * wid + lane;      // scan query (lanes < 16 only)

    const uint32_t khb = sb + KH_OFF;
    const uint32_t vhb = sb + VH_OFF;
    const uint32_t whb = sb + WH_OFF;
    const int lrow = tid >> 2;           // K/V loader row 0..63
    const int lqt  = tid & 3;            // quarter-row (16 floats)

    const int nchunk = 2 * qt + 2;
    for (int h = 0; h < nchunk; h++) {
        const int k0 = h * TK;
        __syncthreads();   // prev chunk's P3 done reading KH/VH

        // ---- load K (RoPE) and V chunk -> fp16 smem (quarter-row/thread) ----
        {
            const float* ksrc = gk + base + (size_t)(k0 + lrow) * HD + lqt * 16;
            const float* vsrc = gv + base + (size_t)(k0 + lrow) * HD + lqt * 16;
            const float* cc   = gcos + (k0 + lrow) * 32 + lqt * 8;
            const float* ss   = gsin + (k0 + lrow) * 32 + lqt * 8;
            __half2* kdst = (__half2*)(smem + KH_OFF + lrow * RSTR + lqt * 32);
            __half2* vdst = (__half2*)(smem + VH_OFF + lrow * RSTR + lqt * 32);
            #pragma unroll
            for (int j = 0; j < 4; j++) {
                float4 x = *(const float4*)(ksrc + 4 * j);
                float2 c = *(const float2*)(cc + 2 * j);
                float2 s = *(const float2*)(ss + 2 * j);
                kdst[2*j]   = __floats2half2_rn(x.x*c.x - x.y*s.x, x.y*c.x + x.x*s.x);
                kdst[2*j+1] = __floats2half2_rn(x.z*c.y - x.w*s.y, x.w*c.y + x.z*s.y);
                float4 v = *(const float4*)(vsrc + 4 * j);
                vdst[2*j]   = __floats2half2_rn(v.x, v.y);
                vdst[2*j+1] = __floats2half2_rn(v.z, v.w);
            }
        }
        __syncthreads();

        // ---- P1: S[16q x 64k] per warp = Q · K^T (HMMA), fused beta -> WH ----
        {
            float sd[8][4];
            #pragma unroll
            for (int nf = 0; nf < 8; nf++)
                #pragma unroll
                for (int r = 0; r < 4; r++) sd[nf][r] = 0.f;

            #pragma unroll
            for (int ks = 0; ks < 4; ks++) {
                uint32_t bf[8][2];
                #pragma unroll
                for (int a2 = 0; a2 < 4; a2++) {
                    uint32_t r[4];
                    int row  = 16 * a2 + (lane & 7) + ((lane & 16) ? 8 : 0);
                    int colb = 32 * ks + ((lane & 8) ? 16 : 0);
                    ldsm4(r, khb + row * RSTR + colb);
                    bf[2*a2][0]   = r[0]; bf[2*a2][1]   = r[1];
                    bf[2*a2+1][0] = r[2]; bf[2*a2+1][1] = r[3];
                }
                #pragma unroll
                for (int nf = 0; nf < 8; nf++)
                    mma16816(sd[nf], qf[ks], bf[nf]);
            }
            // beta epilogue: thread holds S[ql, kl..kl+1] and S[ql+8, ...]
            const int ql = 16 * wid + (lane >> 2);
            const float pda = (float)(k0 - (q0 + ql)) * LAM;
            const float pdb = pda - 8.f * LAM;
            #pragma unroll
            for (int nf = 0; nf < 8; nf++) {
                const int kl = 8 * nf + 2 * (lane & 3);
                float p0 = pda + (float)kl * LAM;
                float b0 = sigm(fminf(fmaxf(fmaf(sd[nf][0], SCALE, p0      ), -CLV), CLV));
                float b1 = sigm(fminf(fmaxf(fmaf(sd[nf][1], SCALE, p0 + LAM), -CLV), CLV));
                *(__half2*)(smem + WH_OFF + ql * RSTR + kl * 2) = __floats2half2_rn(b0, b1);
                float p1 = pdb + (float)kl * LAM;
                float b2 = sigm(fminf(fmaxf(fmaf(sd[nf][2], SCALE, p1      ), -CLV), CLV));
                float b3 = sigm(fminf(fmaxf(fmaf(sd[nf][3], SCALE, p1 + LAM), -CLV), CLV));
                *(__half2*)(smem + WH_OFF + (ql + 8) * RSTR + kl * 2) = __floats2half2_rn(b2, b3);
            }
        }
        __syncwarp();

        // ---- scan: lanes < 16, thread = query sq (warp-local rows) ----
        if (lane < 16) {
            const int nvalid = min(64, max(0, sq + q0 - k0 + 1));
            uint4* wr = (uint4*)(smem + WH_OFF + sq * RSTR);
            #pragma unroll
            for (int g = 0; g < 8; g++) {
                uint4 u = wr[g];
                uint32_t* uw = (uint32_t*)&u;
                #pragma unroll
                for (int m = 0; m < 4; m++) {
                    float2 f = __half22float2(*(__half2*)&uw[m]);
                    int i = g * 8 + m * 2;
                    float w0 = (i < nvalid) ? f.x * rem : 0.f;
                    rem = fmaf(-w0, rem, rem);
                    float w1 = (i + 1 < nvalid) ? f.y * rem : 0.f;
                    rem = fmaf(-w1, rem, rem);
                    ws += w0 + w1;
                    __half2 o = __floats2half2_rn(w0, w1);
                    uw[m] = *(uint32_t*)&o;
                }
                rem = fmaxf(rem, EPSV);
                wr[g] = u;
            }
        }
        __syncwarp();

        // ---- P3: O[16q x 64d] per warp += W · V (HMMA over keys) ----
        #pragma unroll
        for (int ks2 = 0; ks2 < 4; ks2++) {
            uint32_t af[4];
            {
                int row  = 16 * wid + (lane & 15);
                int colb = 32 * ks2 + ((lane & 16) ? 16 : 0);
                ldsm4(af, whb + row * RSTR + colb);
            }
            uint32_t vb[8][2];
            #pragma unroll
            for (int c2 = 0; c2 < 4; c2++) {
                uint32_t r[4];
                int row  = 16 * ks2 + (lane & 7) + ((lane & 8) ? 8 : 0);
                int colb = 32 * c2 + ((lane & 16) ? 16 : 0);
                ldsm4t(r, vhb + row * RSTR + colb);
                vb[2*c2][0]   = r[0]; vb[2*c2][1]   = r[1];
                vb[2*c2+1][0] = r[2]; vb[2*c2+1][1] = r[3];
            }
            #pragma unroll
            for (int c = 0; c < 8; c++)
                mma16816(od[c], af, vb[c]);
        }
    }

    // ---- epilogue: share wsum, normalize O fragments, write out ----
    {
        float* wsF = (float*)(smem + WS_OFF);
        if (lane < 16) wsF[sq] = ws;
        __syncthreads();
        const int ql = 16 * wid + (lane >> 2);
        float inv0 = __fdividef(1.f, fmaxf(wsF[ql],     EPSV));
        float inv1 = __fdividef(1.f, fmaxf(wsF[ql + 8], EPSV));
        float* r0 = gout + base + (size_t)(q0 + ql) * HD;
        float* r1 = r0 + 8 * HD;
        #pragma unroll
        for (int c = 0; c < 8; c++) {
            const int dc = 8 * c + 2 * (lane & 3);
            float2 o0; o0.x = od[c][0] * inv0; o0.y = od[c][1] * inv0;
            *(float2*)(r0 + dc) = o0;
            float2 o1; o1.x = od[c][2] * inv1; o1.y = od[c][3] * inv1;
            *(float2*)(r1 + dc) = o1;
        }
    }
}

extern "C" void kernel_launch(void* const* d_in, const int* in_sizes, int n_in,
                              void* d_out, int out_size)
{
    (void)in_sizes; (void)n_in; (void)out_size;
    const float* q    = (const float*)d_in[0];
    const float* k    = (const float*)d_in[1];
    const float* v    = (const float*)d_in[2];
    const float* cosc = (const float*)d_in[3];
    const float* sinc = (const float*)d_in[4];
    float* out = (float*)d_out;

    cudaFuncSetAttribute(rse_mma, cudaFuncAttributeMaxDynamicSharedMemorySize,
                         SM_TOTAL);
    rse_mma<<<NQT * BHN, NTH, SM_TOTAL>>>(q, k, v, cosc, sinc, out);
}